// round 2
// baseline (speedup 1.0000x reference)
#include <cuda_runtime.h>

#define N_MAX 4096
#define D 1024
#define THR 0.25f
#define ROUNDS 4
#define K_TOP 16

// ---------------- device state (static scratch; no runtime allocation) ----------------
__device__ float g_emb[N_MAX * D];                       // 16 MB working embeddings (global index space)
__device__ float g_ec[N_MAX * D];                        // 16 MB compacted embeddings (zero-padded to N_MAX rows)
__device__ float g_sim[(size_t)N_MAX * N_MAX];           // 64 MB similarity scratch (compacted, stride N_MAX)
__device__ unsigned long long g_topkey[N_MAX * K_TOP];   // per-row top-K packed (val<<32 | ~b)
__device__ unsigned char g_trunc[N_MAX];                 // row had > K_TOP candidates
__device__ int g_idx[N_MAX];                             // compacted -> global index
__device__ int g_partner[N_MAX];                         // compacted partner index or -1
__device__ unsigned char g_alive[N_MAX];
__device__ int g_m;                                      // alive count
__device__ int g_done;

// ---------------- init ----------------
__global__ void k_init(const float* __restrict__ in) {
    int i = blockIdx.x * blockDim.x + threadIdx.x;
    int stride = gridDim.x * blockDim.x;
    for (int t = i; t < N_MAX * D; t += stride) g_emb[t] = in[t];
    if (i < N_MAX) g_alive[i] = 1;
    if (i == 0) g_done = 0;
}

// ---------------- compact alive indices (order-preserving) ----------------
__global__ void k_compact() {  // <<<1,1024>>>
    if (g_done) return;
    __shared__ int wsum[32];
    int tid = threadIdx.x;
    int base = tid * 4;
    int f0 = g_alive[base + 0];
    int f1 = g_alive[base + 1];
    int f2 = g_alive[base + 2];
    int f3 = g_alive[base + 3];
    int cnt = f0 + f1 + f2 + f3;
    int lane = tid & 31, wid = tid >> 5;
    int inc = cnt;
#pragma unroll
    for (int off = 1; off < 32; off <<= 1) {
        int u = __shfl_up_sync(0xFFFFFFFFu, inc, off);
        if (lane >= off) inc += u;
    }
    if (lane == 31) wsum[wid] = inc;
    __syncthreads();
    if (wid == 0) {
        int v = wsum[lane];
#pragma unroll
        for (int off = 1; off < 32; off <<= 1) {
            int u = __shfl_up_sync(0xFFFFFFFFu, v, off);
            if (lane >= off) v += u;
        }
        wsum[lane] = v;
    }
    __syncthreads();
    int ex = inc - cnt + (wid ? wsum[wid - 1] : 0);
    if (f0) g_idx[ex++] = base + 0;
    if (f1) g_idx[ex++] = base + 1;
    if (f2) g_idx[ex++] = base + 2;
    if (f3) g_idx[ex++] = base + 3;
    if (tid == 0) g_m = wsum[31];
}

// ---------------- gather compacted rows (zero-pad to N_MAX) ----------------
__global__ void k_gather() {  // <<<N_MAX, 256>>>
    if (g_done) return;
    int row = blockIdx.x;
    int m = g_m;
    float4* dst = (float4*)(g_emb + 0);  // silence unused warning path
    (void)dst;
    float4* d = (float4*)(g_ec + (size_t)row * D);
    if (row < m) {
        const float4* s = (const float4*)(g_emb + (size_t)g_idx[row] * D);
        d[threadIdx.x] = s[threadIdx.x];
    } else {
        d[threadIdx.x] = make_float4(0.f, 0.f, 0.f, 0.f);
    }
}

// ---------------- fp32 SGEMM: sim[a][b] = dot(ec[a],ec[b])/D, upper-triangle tiles ----------------
__global__ void __launch_bounds__(256) k_gemm() {  // grid (32,32), 256 thr
    if (g_done) return;
    int m = g_m;
    int by = blockIdx.y;  // a tile (rows)
    int bx = blockIdx.x;  // b tile (cols)
    if (bx < by) return;
    if (by * 128 >= m || bx * 128 >= m) return;

    __shared__ float As[16][132];
    __shared__ float Bs[16][132];
    int tid = threadIdx.x;
    int lr = tid >> 2;   // 0..63
    int lq = tid & 3;    // float4 slot in k-chunk
    int ty = tid >> 4;   // 0..15
    int tx = tid & 15;   // 0..15

    const float* Abase = g_ec + (size_t)(by * 128) * D;
    const float* Bbase = g_ec + (size_t)(bx * 128) * D;

    float acc[8][8] = {};

    for (int k0 = 0; k0 < D; k0 += 16) {
        float4 av0 = *(const float4*)(Abase + (size_t)lr * D + k0 + lq * 4);
        float4 av1 = *(const float4*)(Abase + (size_t)(lr + 64) * D + k0 + lq * 4);
        float4 bv0 = *(const float4*)(Bbase + (size_t)lr * D + k0 + lq * 4);
        float4 bv1 = *(const float4*)(Bbase + (size_t)(lr + 64) * D + k0 + lq * 4);
        __syncthreads();
        As[lq * 4 + 0][lr] = av0.x; As[lq * 4 + 1][lr] = av0.y;
        As[lq * 4 + 2][lr] = av0.z; As[lq * 4 + 3][lr] = av0.w;
        As[lq * 4 + 0][lr + 64] = av1.x; As[lq * 4 + 1][lr + 64] = av1.y;
        As[lq * 4 + 2][lr + 64] = av1.z; As[lq * 4 + 3][lr + 64] = av1.w;
        Bs[lq * 4 + 0][lr] = bv0.x; Bs[lq * 4 + 1][lr] = bv0.y;
        Bs[lq * 4 + 2][lr] = bv0.z; Bs[lq * 4 + 3][lr] = bv0.w;
        Bs[lq * 4 + 0][lr + 64] = bv1.x; Bs[lq * 4 + 1][lr + 64] = bv1.y;
        Bs[lq * 4 + 2][lr + 64] = bv1.z; Bs[lq * 4 + 3][lr + 64] = bv1.w;
        __syncthreads();
#pragma unroll
        for (int kk = 0; kk < 16; ++kk) {
            float ra[8], rb[8];
#pragma unroll
            for (int i = 0; i < 8; ++i) ra[i] = As[kk][ty * 8 + i];
#pragma unroll
            for (int j = 0; j < 8; ++j) rb[j] = Bs[kk][tx * 8 + j];
#pragma unroll
            for (int i = 0; i < 8; ++i)
#pragma unroll
                for (int j = 0; j < 8; ++j) acc[i][j] += ra[i] * rb[j];
        }
    }

    const float s = 1.0f / (float)D;
#pragma unroll
    for (int i = 0; i < 8; ++i) {
        int a = by * 128 + ty * 8 + i;
        float* out = g_sim + (size_t)a * N_MAX + bx * 128 + tx * 8;
#pragma unroll
        for (int j = 0; j < 8; ++j) out[j] = acc[i][j] * s;
    }
}

// ---------------- per-row top-K (packed keys; first-occurrence argmax tie-break) ----------------
__global__ void k_topk() {  // <<<N_MAX/8, 256>>>
    if (g_done) return;
    int m = g_m;
    int warp = threadIdx.x >> 5;
    int lane = threadIdx.x & 31;
    int a = blockIdx.x * 8 + warp;
    if (a >= m) return;

    unsigned long long loc[K_TOP];
#pragma unroll
    for (int t = 0; t < K_TOP; ++t) loc[t] = 0ULL;

    const float* row = g_sim + (size_t)a * N_MAX;
    for (int b = a + 1 + lane; b < m; b += 32) {
        unsigned int vb = __float_as_uint(row[b]);  // sims are >= 0 -> monotone as uint
        unsigned long long key =
            ((unsigned long long)vb << 32) | (unsigned int)(0xFFFFFFFFu - (unsigned)b);
        if (key > loc[K_TOP - 1]) {
            loc[K_TOP - 1] = key;
#pragma unroll
            for (int t = K_TOP - 1; t > 0; --t) {
                if (loc[t] > loc[t - 1]) {
                    unsigned long long tmp = loc[t];
                    loc[t] = loc[t - 1];
                    loc[t - 1] = tmp;
                }
            }
        }
    }

    unsigned long long mykey = 0ULL;
#pragma unroll
    for (int s = 0; s < K_TOP; ++s) {
        unsigned long long h = loc[0];
#pragma unroll
        for (int off = 16; off > 0; off >>= 1) {
            unsigned long long o = __shfl_xor_sync(0xFFFFFFFFu, h, off);
            if (o > h) h = o;
        }
        if (lane == s) mykey = h;
        unsigned ball = __ballot_sync(0xFFFFFFFFu, (loc[0] == h) && (h != 0ULL));
        int wl = ball ? (__ffs(ball) - 1) : -1;
        if (lane == wl) {
#pragma unroll
            for (int t = 0; t < K_TOP - 1; ++t) loc[t] = loc[t + 1];
            loc[K_TOP - 1] = 0ULL;
        }
    }
    if (lane < K_TOP) g_topkey[a * K_TOP + lane] = mykey;
    if (lane == 0) g_trunc[a] = (unsigned char)((m - 1 - a) > K_TOP);
}

// ---------------- sequential greedy matching (single warp, exact) ----------------
__global__ void k_seq() {  // <<<1,32>>>
    int lane = threadIdx.x;
    if (g_done) {
        for (int a = lane; a < N_MAX; a += 32) g_partner[a] = -1;
        return;
    }
    volatile __shared__ unsigned int consumed[N_MAX / 32];
    __shared__ unsigned long long keys[32 * K_TOP];
    for (int t = lane; t < N_MAX / 32; t += 32) consumed[t] = 0u;
    __syncwarp();

    int m = g_m;
    int merges = 0;

    for (int a0 = 0; a0 < m; a0 += 32) {
        const ulonglong2* src = (const ulonglong2*)(g_topkey + (size_t)a0 * K_TOP);
        ulonglong2* dst = (ulonglong2*)keys;
        for (int t = lane; t < (32 * K_TOP) / 2; t += 32) dst[t] = src[t];
        __syncwarp();

        int aend = (a0 + 32 < m) ? (a0 + 32) : m;
        for (int a = a0; a < aend; ++a) {
            int partner = -1;
            bool ca = (consumed[a >> 5] >> (a & 31)) & 1u;
            if (!ca) {
                const unsigned long long* kl = keys + (size_t)(a - a0) * K_TOP;
                int foundb = -1;
                float foundv = 0.f;
                bool exhausted = true;
#pragma unroll
                for (int k = 0; k < K_TOP; ++k) {
                    unsigned long long key = kl[k];
                    if (key == 0ULL) { exhausted = false; break; }  // complete list ended
                    int b = (int)(0xFFFFFFFFu - (unsigned int)(key & 0xFFFFFFFFull));
                    if (!((consumed[b >> 5] >> (b & 31)) & 1u)) {
                        foundb = b;
                        foundv = __uint_as_float((unsigned int)(key >> 32));
                        exhausted = false;
                        break;
                    }
                }
                if (foundb >= 0) {
                    if (foundv >= THR) partner = foundb;
                } else if (exhausted && g_trunc[a]) {
                    // rare fallback: all top-K consumed on a truncated list -> full rescan
                    unsigned long long bk = 0ULL;
                    const float* row = g_sim + (size_t)a * N_MAX;
                    for (int b = a + 1 + lane; b < m; b += 32) {
                        if (!((consumed[b >> 5] >> (b & 31)) & 1u)) {
                            unsigned long long key =
                                ((unsigned long long)__float_as_uint(row[b]) << 32) |
                                (unsigned int)(0xFFFFFFFFu - (unsigned)b);
                            if (key > bk) bk = key;
                        }
                    }
#pragma unroll
                    for (int off = 16; off > 0; off >>= 1) {
                        unsigned long long o = __shfl_xor_sync(0xFFFFFFFFu, bk, off);
                        if (o > bk) bk = o;
                    }
                    if (bk != 0ULL) {
                        float v = __uint_as_float((unsigned int)(bk >> 32));
                        if (v >= THR)
                            partner = (int)(0xFFFFFFFFu - (unsigned int)(bk & 0xFFFFFFFFull));
                    }
                }
            }
            if (partner >= 0) {
                ++merges;
                if (lane == 0) consumed[partner >> 5] |= (1u << (partner & 31));
            }
            if (lane == 0) g_partner[a] = partner;
            __syncwarp();
        }
    }
    for (int a = m + lane; a < N_MAX; a += 32) g_partner[a] = -1;
    if (lane == 0) {
        int newcount = m - merges;
        if (merges == 0 || newcount <= 1) g_done = 1;
    }
}

// ---------------- apply merges: fuse initiator, zero+kill partner ----------------
__global__ void k_apply() {  // <<<N_MAX, 256>>>
    int a = blockIdx.x;
    int p = g_partner[a];
    if (p < 0) return;
    int gi = g_idx[a];
    int gj = g_idx[p];
    float4* vi = (float4*)(g_emb + (size_t)gi * D);
    float4* vj = (float4*)(g_emb + (size_t)gj * D);
    int t = threadIdx.x;
    float4 x = vi[t];
    float4 y = vj[t];
    x.x = fminf(x.x + y.x, 1.0f);
    x.y = fminf(x.y + y.y, 1.0f);
    x.z = fminf(x.z + y.z, 1.0f);
    x.w = fminf(x.w + y.w, 1.0f);
    vi[t] = x;
    vj[t] = make_float4(0.f, 0.f, 0.f, 0.f);
    if (t == 0) g_alive[gj] = 0;
}

// ---------------- write output: emb then alive (as float) ----------------
__global__ void k_output(float* __restrict__ out, int out_size) {
    int i = blockIdx.x * blockDim.x + threadIdx.x;
    int stride = gridDim.x * blockDim.x;
    for (int t = i; t < N_MAX * D; t += stride)
        if (t < out_size) out[t] = g_emb[t];
    for (int r = i; r < N_MAX; r += stride) {
        int o = N_MAX * D + r;
        if (o < out_size) out[o] = g_alive[r] ? 1.0f : 0.0f;
    }
}

extern "C" void kernel_launch(void* const* d_in, const int* in_sizes, int n_in,
                              void* d_out, int out_size) {
    const float* in = (const float*)d_in[0];
    k_init<<<4096, 256>>>(in);
    for (int r = 0; r < ROUNDS; ++r) {
        k_compact<<<1, 1024>>>();
        k_gather<<<N_MAX, 256>>>();
        dim3 grid(32, 32);
        k_gemm<<<grid, 256>>>();
        k_topk<<<N_MAX / 8, 256>>>();
        k_seq<<<1, 32>>>();
        k_apply<<<N_MAX, 256>>>();
    }
    k_output<<<4096, 256>>>((float*)d_out, out_size);
}

// round 3
// speedup vs baseline: 7.0578x; 7.0578x over previous
#include <cuda_runtime.h>

#define N_MAX 4096
#define D 1024
#define THR 0.25f
#define ROUNDS 4
#define K_TOP 16
#define FULLMASK 0xFFFFFFFFu

#define BARRIER() asm volatile("bar.sync 0;" ::: "memory")

// ---------------- device state (static scratch; no runtime allocation) ----------------
__device__ float g_emb[N_MAX * D];                       // working embeddings (global index space)
__device__ float g_ec[N_MAX * D];                        // compacted embeddings (zero-padded)
__device__ float g_sim[(size_t)N_MAX * N_MAX];           // similarity scratch (compacted, stride N_MAX)
__device__ unsigned long long g_topkey[N_MAX * K_TOP];   // per-row top-K packed (val<<32 | ~b)
__device__ int g_idx[N_MAX];                             // compacted -> global index
__device__ int g_partner[N_MAX];                         // compacted partner index or -1
__device__ unsigned char g_alive[N_MAX];
__device__ int g_m;                                      // alive count
__device__ int g_done;

// ---------------- init ----------------
__global__ void k_init(const float* __restrict__ in) {
    int i = blockIdx.x * blockDim.x + threadIdx.x;
    int stride = gridDim.x * blockDim.x;
    for (int t = i; t < N_MAX * D; t += stride) g_emb[t] = in[t];
    if (i < N_MAX) g_alive[i] = 1;
    if (i == 0) g_done = 0;
}

// ---------------- compact alive indices (order-preserving) ----------------
__global__ void k_compact() {  // <<<1,1024>>>
    if (g_done) return;
    __shared__ int wsum[32];
    int tid = threadIdx.x;
    int base = tid * 4;
    int f0 = g_alive[base + 0];
    int f1 = g_alive[base + 1];
    int f2 = g_alive[base + 2];
    int f3 = g_alive[base + 3];
    int cnt = f0 + f1 + f2 + f3;
    int lane = tid & 31, wid = tid >> 5;
    int inc = cnt;
#pragma unroll
    for (int off = 1; off < 32; off <<= 1) {
        int u = __shfl_up_sync(FULLMASK, inc, off);
        if (lane >= off) inc += u;
    }
    if (lane == 31) wsum[wid] = inc;
    __syncthreads();
    if (wid == 0) {
        int v = wsum[lane];
#pragma unroll
        for (int off = 1; off < 32; off <<= 1) {
            int u = __shfl_up_sync(FULLMASK, v, off);
            if (lane >= off) v += u;
        }
        wsum[lane] = v;
    }
    __syncthreads();
    int ex = inc - cnt + (wid ? wsum[wid - 1] : 0);
    if (f0) g_idx[ex++] = base + 0;
    if (f1) g_idx[ex++] = base + 1;
    if (f2) g_idx[ex++] = base + 2;
    if (f3) g_idx[ex++] = base + 3;
    if (tid == 0) g_m = wsum[31];
}

// ---------------- gather compacted rows (zero-pad to N_MAX) ----------------
__global__ void k_gather() {  // <<<N_MAX, 256>>>
    if (g_done) return;
    int row = blockIdx.x;
    int m = g_m;
    float4* d = (float4*)(g_ec + (size_t)row * D);
    if (row < m) {
        const float4* s = (const float4*)(g_emb + (size_t)g_idx[row] * D);
        d[threadIdx.x] = s[threadIdx.x];
    } else {
        d[threadIdx.x] = make_float4(0.f, 0.f, 0.f, 0.f);
    }
}

// ---------------- fp32 SGEMM: sim[a][b] = dot(ec[a],ec[b])/D, upper-triangle tiles ----------------
__global__ void __launch_bounds__(256) k_gemm() {  // grid (32,32), 256 thr
    if (g_done) return;
    int m = g_m;
    int by = blockIdx.y;  // a tile (rows)
    int bx = blockIdx.x;  // b tile (cols)
    if (bx < by) return;
    if (by * 128 >= m || bx * 128 >= m) return;

    __shared__ float As[16][132];
    __shared__ float Bs[16][132];
    int tid = threadIdx.x;
    int lr = tid >> 2;   // 0..63
    int lq = tid & 3;    // float4 slot in k-chunk
    int ty = tid >> 4;   // 0..15
    int tx = tid & 15;   // 0..15

    const float* Abase = g_ec + (size_t)(by * 128) * D;
    const float* Bbase = g_ec + (size_t)(bx * 128) * D;

    float acc[8][8] = {};

    for (int k0 = 0; k0 < D; k0 += 16) {
        float4 av0 = *(const float4*)(Abase + (size_t)lr * D + k0 + lq * 4);
        float4 av1 = *(const float4*)(Abase + (size_t)(lr + 64) * D + k0 + lq * 4);
        float4 bv0 = *(const float4*)(Bbase + (size_t)lr * D + k0 + lq * 4);
        float4 bv1 = *(const float4*)(Bbase + (size_t)(lr + 64) * D + k0 + lq * 4);
        __syncthreads();
        As[lq * 4 + 0][lr] = av0.x; As[lq * 4 + 1][lr] = av0.y;
        As[lq * 4 + 2][lr] = av0.z; As[lq * 4 + 3][lr] = av0.w;
        As[lq * 4 + 0][lr + 64] = av1.x; As[lq * 4 + 1][lr + 64] = av1.y;
        As[lq * 4 + 2][lr + 64] = av1.z; As[lq * 4 + 3][lr + 64] = av1.w;
        Bs[lq * 4 + 0][lr] = bv0.x; Bs[lq * 4 + 1][lr] = bv0.y;
        Bs[lq * 4 + 2][lr] = bv0.z; Bs[lq * 4 + 3][lr] = bv0.w;
        Bs[lq * 4 + 0][lr + 64] = bv1.x; Bs[lq * 4 + 1][lr + 64] = bv1.y;
        Bs[lq * 4 + 2][lr + 64] = bv1.z; Bs[lq * 4 + 3][lr + 64] = bv1.w;
        __syncthreads();
#pragma unroll
        for (int kk = 0; kk < 16; ++kk) {
            float ra[8], rb[8];
#pragma unroll
            for (int i = 0; i < 8; ++i) ra[i] = As[kk][ty * 8 + i];
#pragma unroll
            for (int j = 0; j < 8; ++j) rb[j] = Bs[kk][tx * 8 + j];
#pragma unroll
            for (int i = 0; i < 8; ++i)
#pragma unroll
                for (int j = 0; j < 8; ++j) acc[i][j] += ra[i] * rb[j];
        }
    }

    const float s = 1.0f / (float)D;
#pragma unroll
    for (int i = 0; i < 8; ++i) {
        int a = by * 128 + ty * 8 + i;
        float* out = g_sim + (size_t)a * N_MAX + bx * 128 + tx * 8;
#pragma unroll
        for (int j = 0; j < 8; ++j) out[j] = acc[i][j] * s;
    }
}

// ---------------- per-row top-K (packed keys; first-occurrence argmax tie-break) ----------------
__global__ void k_topk() {  // <<<N_MAX/8, 256>>>
    if (g_done) return;
    int m = g_m;
    int warp = threadIdx.x >> 5;
    int lane = threadIdx.x & 31;
    int a = blockIdx.x * 8 + warp;
    if (a >= m) return;

    unsigned long long loc[K_TOP];
#pragma unroll
    for (int t = 0; t < K_TOP; ++t) loc[t] = 0ULL;

    const float* row = g_sim + (size_t)a * N_MAX;
    for (int b = a + 1 + lane; b < m; b += 32) {
        unsigned int vb = __float_as_uint(row[b]);  // sims >= 0 -> monotone as uint
        unsigned long long key =
            ((unsigned long long)vb << 32) | (unsigned int)(0xFFFFFFFFu - (unsigned)b);
        if (key > loc[K_TOP - 1]) {
            loc[K_TOP - 1] = key;
#pragma unroll
            for (int t = K_TOP - 1; t > 0; --t) {
                if (loc[t] > loc[t - 1]) {
                    unsigned long long tmp = loc[t];
                    loc[t] = loc[t - 1];
                    loc[t - 1] = tmp;
                }
            }
        }
    }

    unsigned long long mykey = 0ULL;
#pragma unroll
    for (int s = 0; s < K_TOP; ++s) {
        unsigned long long h = loc[0];
#pragma unroll
        for (int off = 16; off > 0; off >>= 1) {
            unsigned long long o = __shfl_xor_sync(FULLMASK, h, off);
            if (o > h) h = o;
        }
        if (lane == s) mykey = h;
        unsigned ball = __ballot_sync(FULLMASK, (loc[0] == h) && (h != 0ULL));
        int wl = ball ? (__ffs(ball) - 1) : -1;
        if (lane == wl) {
#pragma unroll
            for (int t = 0; t < K_TOP - 1; ++t) loc[t] = loc[t + 1];
            loc[K_TOP - 1] = 0ULL;
        }
    }
    if (lane < K_TOP) g_topkey[a * K_TOP + lane] = mykey;
}

// ---------------- sequential greedy matching: 1 block, warp0 drives, block-wide fallback ----
__global__ void __launch_bounds__(1024, 1) k_seq2() {  // <<<1,1024>>>
    __shared__ volatile unsigned int consumed[N_MAX / 32];
    __shared__ unsigned long long partial[32];
    __shared__ int s_cmd;   // 1 = fallback scan, 2 = exit
    __shared__ int s_row;

    int tid = threadIdx.x, lane = tid & 31, wid = tid >> 5;

    if (g_done) {
        for (int a = tid; a < N_MAX; a += 1024) g_partner[a] = -1;
        return;
    }
    int m = g_m;
    for (int t = tid; t < N_MAX / 32; t += 1024) consumed[t] = 0u;
    __syncthreads();

    if (wid == 0) {
        // -------- warp 0: sequential driver --------
        int merges = 0;
        unsigned long long kcur =
            (lane < K_TOP && 0 < m) ? g_topkey[0 * K_TOP + lane] : 0ULL;
        unsigned long long knext =
            (lane < K_TOP && 1 < m) ? g_topkey[1 * K_TOP + lane] : 0ULL;

        for (int a = 0; a < m; ++a) {
            unsigned long long knext2 =
                (lane < K_TOP && a + 2 < m) ? g_topkey[(size_t)(a + 2) * K_TOP + lane] : 0ULL;

            int b = (int)(0xFFFFFFFFu - (unsigned int)(kcur & 0xFFFFFFFFull));
            bool valid = (lane < K_TOP) && (kcur != 0ULL);
            bool avail = valid && !((consumed[b >> 5] >> (b & 31)) & 1u);
            unsigned ball_avail = __ballot_sync(FULLMASK, avail);
            unsigned ball_zero = __ballot_sync(FULLMASK, (lane < K_TOP) && (kcur == 0ULL));
            bool ca = (consumed[a >> 5] >> (a & 31)) & 1u;  // lane-uniform

            int partner = -1;
            if (!ca) {
                if (ball_avail) {
                    int f = __ffs(ball_avail) - 1;
                    unsigned long long kf = __shfl_sync(FULLMASK, kcur, f);
                    float v = __uint_as_float((unsigned int)(kf >> 32));
                    if (v >= THR)
                        partner = (int)(0xFFFFFFFFu - (unsigned int)(kf & 0xFFFFFFFFull));
                } else if (ball_zero == 0 && (m - 1 - a) > K_TOP) {
                    // ---- block-wide fallback rescan of row a ----
                    if (lane == 0) { s_cmd = 1; s_row = a; }
                    BARRIER();  // engage parked warps
                    {
                        unsigned long long best = 0ULL;
                        const float* row = g_sim + (size_t)a * N_MAX;
                        for (int bb = a + 1 + tid; bb < m; bb += 1024) {
                            if (!((consumed[bb >> 5] >> (bb & 31)) & 1u)) {
                                unsigned long long key =
                                    ((unsigned long long)__float_as_uint(row[bb]) << 32) |
                                    (unsigned int)(0xFFFFFFFFu - (unsigned)bb);
                                if (key > best) best = key;
                            }
                        }
#pragma unroll
                        for (int off = 16; off > 0; off >>= 1) {
                            unsigned long long o = __shfl_xor_sync(FULLMASK, best, off);
                            if (o > best) best = o;
                        }
                        if (lane == 0) partial[wid] = best;
                    }
                    BARRIER();  // scan complete
                    unsigned long long p = partial[lane];
#pragma unroll
                    for (int off = 16; off > 0; off >>= 1) {
                        unsigned long long o = __shfl_xor_sync(FULLMASK, p, off);
                        if (o > p) p = o;
                    }
                    if (p != 0ULL) {
                        float v = __uint_as_float((unsigned int)(p >> 32));
                        if (v >= THR)
                            partner = (int)(0xFFFFFFFFu - (unsigned int)(p & 0xFFFFFFFFull));
                    }
                }
            }
            if (partner >= 0) {
                ++merges;
                if (lane == 0) consumed[partner >> 5] |= (1u << (partner & 31));
            }
            if (lane == 0) g_partner[a] = partner;
            __syncwarp();
            kcur = knext;
            knext = knext2;
        }
        if (lane == 0) s_cmd = 2;
        BARRIER();  // release parked warps to exit
        for (int a = m + lane; a < N_MAX; a += 32) g_partner[a] = -1;
        if (lane == 0) {
            if (merges == 0 || (m - merges) <= 1) g_done = 1;
        }
    } else {
        // -------- warps 1..31: parked, service fallback scans --------
        while (true) {
            BARRIER();
            int cmd = s_cmd;
            if (cmd == 2) break;
            int a = s_row;
            unsigned long long best = 0ULL;
            const float* row = g_sim + (size_t)a * N_MAX;
            for (int bb = a + 1 + tid; bb < m; bb += 1024) {
                if (!((consumed[bb >> 5] >> (bb & 31)) & 1u)) {
                    unsigned long long key =
                        ((unsigned long long)__float_as_uint(row[bb]) << 32) |
                        (unsigned int)(0xFFFFFFFFu - (unsigned)bb);
                    if (key > best) best = key;
                }
            }
#pragma unroll
            for (int off = 16; off > 0; off >>= 1) {
                unsigned long long o = __shfl_xor_sync(FULLMASK, best, off);
                if (o > best) best = o;
            }
            if (lane == 0) partial[wid] = best;
            BARRIER();
        }
    }
}

// ---------------- apply merges: fuse initiator, zero+kill partner ----------------
__global__ void k_apply() {  // <<<N_MAX, 256>>>
    int a = blockIdx.x;
    int p = g_partner[a];
    if (p < 0) return;
    int gi = g_idx[a];
    int gj = g_idx[p];
    float4* vi = (float4*)(g_emb + (size_t)gi * D);
    float4* vj = (float4*)(g_emb + (size_t)gj * D);
    int t = threadIdx.x;
    float4 x = vi[t];
    float4 y = vj[t];
    x.x = fminf(x.x + y.x, 1.0f);
    x.y = fminf(x.y + y.y, 1.0f);
    x.z = fminf(x.z + y.z, 1.0f);
    x.w = fminf(x.w + y.w, 1.0f);
    vi[t] = x;
    vj[t] = make_float4(0.f, 0.f, 0.f, 0.f);
    if (t == 0) g_alive[gj] = 0;
}

// ---------------- write output: emb then alive (as float) ----------------
__global__ void k_output(float* __restrict__ out, int out_size) {
    int i = blockIdx.x * blockDim.x + threadIdx.x;
    int stride = gridDim.x * blockDim.x;
    for (int t = i; t < N_MAX * D; t += stride)
        if (t < out_size) out[t] = g_emb[t];
    for (int r = i; r < N_MAX; r += stride) {
        int o = N_MAX * D + r;
        if (o < out_size) out[o] = g_alive[r] ? 1.0f : 0.0f;
    }
}

extern "C" void kernel_launch(void* const* d_in, const int* in_sizes, int n_in,
                              void* d_out, int out_size) {
    const float* in = (const float*)d_in[0];
    k_init<<<4096, 256>>>(in);
    for (int r = 0; r < ROUNDS; ++r) {
        k_compact<<<1, 1024>>>();
        k_gather<<<N_MAX, 256>>>();
        dim3 grid(32, 32);
        k_gemm<<<grid, 256>>>();
        k_topk<<<N_MAX / 8, 256>>>();
        k_seq2<<<1, 1024>>>();
        k_apply<<<N_MAX, 256>>>();
    }
    k_output<<<4096, 256>>>((float*)d_out, out_size);
}